// round 4
// baseline (speedup 1.0000x reference)
#include <cuda_runtime.h>
#include <cuda_bf16.h>

// SpanIndexEncoder, fully fused single-kernel version.
// out[t] = sum over nodes n (n<num_nodes, s_n<=t<=e_n) of emb[n]
// Phases inside ONE persistent kernel (512 blocks x 128 thr, guaranteed co-resident):
//   P0: zero diff array (= d_out)
//   P1: scatter red.v4 {+emb at s, -emb at e+1} into diff
//   P2a: block b sums its chunk's 16 diff rows (ld.global.cv), keeps rows in regs
//   P2b: warp-per-feature exclusive scan of 512 chunk sums
//   P3: apply: run = prefix; chain over cached rows; store
// Grid barrier: monotonic global counter, phase-windowed -> valid across graph replays.

#define MAX_TOKENS 8192
#define MAX_NODES  8192
#define FEAT       256
#define CHUNK      16
#define NCHUNK     (MAX_TOKENS / CHUNK)   // 512
#define GRID       NCHUNK                 // 512 blocks
#define BLOCK      128

__device__ float    g_chunk[NCHUNK * FEAT];  // chunk sums -> exclusive prefixes
__device__ unsigned g_count;                 // monotonic barrier counter

__device__ __forceinline__ void red_add_v4(float* p, float a, float b, float c, float d) {
    asm volatile("red.global.add.v4.f32 [%0], {%1,%2,%3,%4};"
                 :: "l"(p), "f"(a), "f"(b), "f"(c), "f"(d) : "memory");
}

// L1-bypassing vector load (atomics & other-block stores only update L2).
__device__ __forceinline__ float4 ldcv_v4(const float* p) {
    float4 r;
    asm volatile("ld.global.cv.v4.f32 {%0,%1,%2,%3}, [%4];"
                 : "=f"(r.x), "=f"(r.y), "=f"(r.z), "=f"(r.w) : "l"(p));
    return r;
}

// Grid-wide barrier. Counter is monotonic; phase target = next multiple of GRID.
// Works across launches/graph replays without reset.
__device__ __forceinline__ void gsync() {
    __syncthreads();
    if (threadIdx.x == 0) {
        __threadfence();
        unsigned v = atomicAdd(&g_count, 1u);
        unsigned target = (v / GRID + 1u) * GRID;
        while (*(volatile unsigned*)&g_count < target) { }
        __threadfence();
    }
    __syncthreads();
}

__global__ void __launch_bounds__(BLOCK, 4) span_fused_kernel(
    const float* __restrict__ emb,
    const int*   __restrict__ starts,
    const int*   __restrict__ ends,
    const int*   __restrict__ num_nodes_p,
    float*       __restrict__ out)
{
    const int b   = blockIdx.x;
    const int tid = threadIdx.x;

    // ---- P0: zero this block's 16 diff rows (16*256 floats = 1024 float4) ----
    {
        float4* p = reinterpret_cast<float4*>(out + (size_t)b * CHUNK * FEAT);
        const float4 z = make_float4(0.f, 0.f, 0.f, 0.f);
#pragma unroll
        for (int i = 0; i < 8; ++i)
            p[tid + i * BLOCK] = z;
    }
    gsync();

    // ---- P1: scatter. 16 nodes per block, 2 nodes per iteration (64 thr each) ----
    {
        const int num_nodes = num_nodes_p[0];
        const int j   = (tid & 63) << 2;   // feature offset (float4)
        const int sub = tid >> 6;          // 0/1: which node of the pair
#pragma unroll
        for (int it = 0; it < 8; ++it) {
            const int n = b * 16 + it * 2 + sub;
            if (n < num_nodes) {
                const int s = starts[n];
                const int e = ends[n];
                if (s <= e) {
                    const float4 v = *reinterpret_cast<const float4*>(emb + (size_t)n * FEAT + j);
                    red_add_v4(out + (size_t)s * FEAT + j, v.x, v.y, v.z, v.w);
                    if (e + 1 < MAX_TOKENS)
                        red_add_v4(out + (size_t)(e + 1) * FEAT + j, -v.x, -v.y, -v.z, -v.w);
                }
            }
        }
    }
    gsync();

    // ---- P2a: chunk sums. tid<64: load chunk b's 16 rows (kept in regs for P3) ----
    float4 v[CHUNK];
    if (tid < 64) {
        const float* p = out + (size_t)b * CHUNK * FEAT + (tid << 2);
#pragma unroll
        for (int t = 0; t < CHUNK; ++t)
            v[t] = ldcv_v4(p + (size_t)t * FEAT);
        float4 s = v[0];
#pragma unroll
        for (int t = 1; t < CHUNK; ++t) {
            s.x += v[t].x; s.y += v[t].y; s.z += v[t].z; s.w += v[t].w;
        }
        *reinterpret_cast<float4*>(&g_chunk[b * FEAT + (tid << 2)]) = s;
    }
    gsync();

    // ---- P2b: exclusive scan over 512 chunk sums; blocks 0..255, warp 2 (tids 64..95) ----
    if (b < FEAT && tid >= 64 && tid < 96) {
        const int f = b;
        const int l = tid - 64;            // lane within warp 2
        const int base = l * 16;

        float w[16];
#pragma unroll
        for (int i = 0; i < 16; ++i) w[i] = g_chunk[(base + i) * FEAT + f];
#pragma unroll
        for (int i = 1; i < 16; ++i) w[i] += w[i - 1];

        float own = w[15];
        float incl = own;
#pragma unroll
        for (int d = 1; d < 32; d <<= 1) {
            float t = __shfl_up_sync(0xffffffffu, incl, d);
            if (l >= d) incl += t;
        }
        const float excl = incl - own;

        g_chunk[(base + 0) * FEAT + f] = excl;
#pragma unroll
        for (int i = 1; i < 16; ++i)
            g_chunk[(base + i) * FEAT + f] = excl + w[i - 1];
    }
    gsync();

    // ---- P3: apply. Prefix + inclusive chain over the register-cached rows ----
    if (tid < 64) {
        float4 run = ldcv_v4(&g_chunk[b * FEAT + (tid << 2)]);   // scan overwrote our L1 line -> cv
        float* p = out + (size_t)b * CHUNK * FEAT + (tid << 2);
#pragma unroll
        for (int t = 0; t < CHUNK; ++t) {
            run.x += v[t].x; run.y += v[t].y; run.z += v[t].z; run.w += v[t].w;
            *reinterpret_cast<float4*>(p + (size_t)t * FEAT) = run;
        }
    }
}

extern "C" void kernel_launch(void* const* d_in, const int* in_sizes, int n_in,
                              void* d_out, int out_size)
{
    const float* emb    = (const float*)d_in[0];
    const int*   starts = (const int*)d_in[1];
    const int*   ends   = (const int*)d_in[2];
    const int*   nnp    = (const int*)d_in[3];
    float*       out    = (float*)d_out;

    span_fused_kernel<<<GRID, BLOCK>>>(emb, starts, ends, nnp, out);
}

// round 5
// speedup vs baseline: 1.2733x; 1.2733x over previous
#include <cuda_runtime.h>
#include <cuda_bf16.h>

// SpanIndexEncoder: out[t] = sum over nodes n (n<num_nodes, s_n<=t<=e_n) of emb[n]
// Sparse-event formulation: only ~2*num_nodes span-boundary events exist.
//   A: classify events into per-chunk compact lists (cheap scalar atomics)
//   B: per-chunk sums by gathering event embedding rows (L2-resident)
//   C: warp-per-feature exclusive scan over 512 chunk sums
//   D: apply: counting-sort chunk events by token, chain prefix + event rows, store out.
//      D resets counters -> no memset node needed (globals zero-init at load).

#define MAX_TOKENS 8192
#define MAX_NODES  8192
#define FEAT       256
#define F4         (FEAT / 4)            // 64 float4 columns
#define CHUNK      16
#define NCHUNK     (MAX_TOKENS / CHUNK)  // 512
#define CAP        16384                 // events per chunk, absolute worst case
#define SH_CAP     2048

// event word: bits[0:13)=node, bits[13:17)=token-within-chunk, bit 17=sign(1=minus)
__device__ unsigned g_ev[NCHUNK * CAP];      // 32 MB event pool
__device__ int      g_cnt[NCHUNK];           // per-chunk event counts (self-resetting)
__device__ float    g_chunk[NCHUNK * FEAT];  // chunk sums -> exclusive prefixes

// ---- A: classify span boundaries into per-chunk lists ----
__global__ void __launch_bounds__(256) classify_kernel(
    const int* __restrict__ starts,
    const int* __restrict__ ends,
    const int* __restrict__ num_nodes_p)
{
    const int n = blockIdx.x * 256 + threadIdx.x;
    if (n >= num_nodes_p[0]) return;
    const int s = starts[n];
    const int e = ends[n];
    if (s > e) return;

    int p = atomicAdd(&g_cnt[s >> 4], 1);
    g_ev[(s >> 4) * CAP + p] = (unsigned)n | ((unsigned)(s & 15) << 13);

    const int e1 = e + 1;
    if (e1 < MAX_TOKENS) {
        p = atomicAdd(&g_cnt[e1 >> 4], 1);
        g_ev[(e1 >> 4) * CAP + p] = (unsigned)n | ((unsigned)(e1 & 15) << 13) | (1u << 17);
    }
}

// ---- B: chunk sums by gathering event rows. 512 blocks x 256 thr (4 event-groups x 64 cols) ----
__global__ void __launch_bounds__(256) chunk_sum_kernel(const float* __restrict__ emb)
{
    const int c   = blockIdx.x;
    const int tid = threadIdx.x;
    const int j   = tid & 63;        // float4 column
    const int grp = tid >> 6;        // 0..3
    int cnt = g_cnt[c]; if (cnt > CAP) cnt = CAP;

    const float4* emb4 = reinterpret_cast<const float4*>(emb);
    float4 s = make_float4(0.f, 0.f, 0.f, 0.f);
    for (int e = grp; e < cnt; e += 4) {
        const unsigned w = g_ev[c * CAP + e];
        const float sg = (w & (1u << 17)) ? -1.f : 1.f;
        const float4 v = emb4[(size_t)(w & 8191u) * F4 + j];
        s.x += sg * v.x; s.y += sg * v.y; s.z += sg * v.z; s.w += sg * v.w;
    }

    __shared__ float4 red[256];
    red[tid] = s;
    __syncthreads();
    if (grp == 0) {
        const float4 a = red[tid], b = red[tid + 64], d = red[tid + 128], f = red[tid + 192];
        s.x = a.x + b.x + d.x + f.x;
        s.y = a.y + b.y + d.y + f.y;
        s.z = a.z + b.z + d.z + f.z;
        s.w = a.w + b.w + d.w + f.w;
        *reinterpret_cast<float4*>(&g_chunk[c * FEAT + (j << 2)]) = s;
    }
}

// ---- C: warp-per-feature exclusive scan over NCHUNK=512 chunk sums ----
__global__ void __launch_bounds__(32) chunk_scan_kernel()
{
    const int f = blockIdx.x;
    const int l = threadIdx.x;
    const int base = l * 16;

    float v[16];
#pragma unroll
    for (int i = 0; i < 16; ++i) v[i] = g_chunk[(base + i) * FEAT + f];
#pragma unroll
    for (int i = 1; i < 16; ++i) v[i] += v[i - 1];

    const float own = v[15];
    float incl = own;
#pragma unroll
    for (int d = 1; d < 32; d <<= 1) {
        const float t = __shfl_up_sync(0xffffffffu, incl, d);
        if (l >= d) incl += t;
    }
    const float excl = incl - own;

    g_chunk[(base + 0) * FEAT + f] = excl;
#pragma unroll
    for (int i = 1; i < 16; ++i)
        g_chunk[(base + i) * FEAT + f] = excl + v[i - 1];
}

// ---- D: apply. 512 blocks x 128 thr. Counting-sort events by token, chain, store. ----
__global__ void __launch_bounds__(128) apply_kernel(
    const float* __restrict__ emb,
    float*       __restrict__ out)
{
    const int c   = blockIdx.x;
    const int tid = threadIdx.x;

    __shared__ int hist[16], off[17], cur[16];
    __shared__ unsigned sev[SH_CAP];

    int cnt = g_cnt[c]; if (cnt > SH_CAP) cnt = SH_CAP;

    if (tid < 16) hist[tid] = 0;
    __syncthreads();
    for (int e = tid; e < cnt; e += 128)
        atomicAdd(&hist[(g_ev[c * CAP + e] >> 13) & 15], 1);
    __syncthreads();
    if (tid == 0) {
        int a = 0;
#pragma unroll
        for (int i = 0; i < 16; ++i) { off[i] = a; cur[i] = a; a += hist[i]; }
        off[16] = a;
    }
    __syncthreads();
    for (int e = tid; e < cnt; e += 128) {
        const unsigned w = g_ev[c * CAP + e];
        sev[atomicAdd(&cur[(w >> 13) & 15], 1)] = w;
    }
    __syncthreads();

    const int j    = tid & 63;       // float4 column
    const int half = tid >> 6;       // tokens [half*8, half*8+8)
    const int t0   = half * 8;
    const float4* emb4 = reinterpret_cast<const float4*>(emb);

    float4 run = *reinterpret_cast<const float4*>(&g_chunk[c * FEAT + (j << 2)]);

    // catch-up: events in tokens [0, t0) (empty for half 0)
    for (int e = 0; e < off[t0]; ++e) {
        const unsigned w = sev[e];
        const float sg = (w & (1u << 17)) ? -1.f : 1.f;
        const float4 v = emb4[(size_t)(w & 8191u) * F4 + j];
        run.x += sg * v.x; run.y += sg * v.y; run.z += sg * v.z; run.w += sg * v.w;
    }
#pragma unroll
    for (int t = 0; t < 8; ++t) {
        const int tt = t0 + t;
        for (int e = off[tt]; e < off[tt + 1]; ++e) {
            const unsigned w = sev[e];
            const float sg = (w & (1u << 17)) ? -1.f : 1.f;
            const float4 v = emb4[(size_t)(w & 8191u) * F4 + j];
            run.x += sg * v.x; run.y += sg * v.y; run.z += sg * v.z; run.w += sg * v.w;
        }
        *reinterpret_cast<float4*>(out + (size_t)(c * CHUNK + tt) * FEAT + (j << 2)) = run;
    }

    // self-reset counters for the next replay (all reads of g_cnt/g_ev for this block are done)
    __syncthreads();
    if (tid == 0) g_cnt[c] = 0;
}

extern "C" void kernel_launch(void* const* d_in, const int* in_sizes, int n_in,
                              void* d_out, int out_size)
{
    const float* emb    = (const float*)d_in[0];
    const int*   starts = (const int*)d_in[1];
    const int*   ends   = (const int*)d_in[2];
    const int*   nnp    = (const int*)d_in[3];
    float*       out    = (float*)d_out;

    classify_kernel<<<MAX_NODES / 256, 256>>>(starts, ends, nnp);
    chunk_sum_kernel<<<NCHUNK, 256>>>(emb);
    chunk_scan_kernel<<<FEAT, 32>>>();
    apply_kernel<<<NCHUNK, 128>>>(emb, out);
}

// round 6
// speedup vs baseline: 1.2947x; 1.0168x over previous
#include <cuda_runtime.h>
#include <cuda_bf16.h>

// SpanIndexEncoder: out[t] = sum over nodes n (n<num_nodes, s_n<=t<=e_n) of emb[n]
// Sparse-event formulation (~2*num_nodes boundary events total):
//   A: classify events into per-chunk compact lists (cheap scalar atomics)
//   B: per-chunk sums by gathering event rows (8-way event-parallel)
//   C: warp-per-feature exclusive scan over 512 chunk sums
//   D: apply: PARALLEL-stage signed event rows into smem at counting-sort slots
//      (independent gathers -> full MLP), then chain prefix + smem adds, store out.
//      D resets counters -> no memset node (globals zero-init at module load).

#define MAX_TOKENS 8192
#define MAX_NODES  8192
#define FEAT       256
#define F4         (FEAT / 4)            // 64 float4 columns
#define CHUNK      16
#define NCHUNK     (MAX_TOKENS / CHUNK)  // 512
#define CAP        16384                 // worst-case events per chunk
#define SH_EV      54                    // staged events (54 KB sdata -> 4 blocks/SM)

// event word: bits[0:13)=node, bits[13:17)=token-within-chunk, bit 17=sign(1=minus)
__device__ unsigned g_ev[NCHUNK * CAP];
__device__ int      g_cnt[NCHUNK];           // self-resetting
__device__ float    g_chunk[NCHUNK * FEAT];  // chunk sums -> exclusive prefixes

// ---- A: classify span boundaries into per-chunk lists ----
__global__ void __launch_bounds__(256) classify_kernel(
    const int* __restrict__ starts,
    const int* __restrict__ ends,
    const int* __restrict__ num_nodes_p)
{
    const int n = blockIdx.x * 256 + threadIdx.x;
    if (n >= num_nodes_p[0]) return;
    const int s = starts[n];
    const int e = ends[n];
    if (s > e) return;

    int p = atomicAdd(&g_cnt[s >> 4], 1);
    g_ev[(s >> 4) * CAP + p] = (unsigned)n | ((unsigned)(s & 15) << 13);

    const int e1 = e + 1;
    if (e1 < MAX_TOKENS) {
        p = atomicAdd(&g_cnt[e1 >> 4], 1);
        g_ev[(e1 >> 4) * CAP + p] = (unsigned)n | ((unsigned)(e1 & 15) << 13) | (1u << 17);
    }
}

// ---- B: chunk sums. 512 blocks x 512 thr (8 event-groups x 64 cols) ----
__global__ void __launch_bounds__(512) chunk_sum_kernel(const float* __restrict__ emb)
{
    const int c   = blockIdx.x;
    const int tid = threadIdx.x;
    const int j   = tid & 63;        // float4 column
    const int grp = tid >> 6;        // 0..7
    int cnt = g_cnt[c]; if (cnt > CAP) cnt = CAP;

    const float4* emb4 = reinterpret_cast<const float4*>(emb);
    float4 s = make_float4(0.f, 0.f, 0.f, 0.f);
    for (int e = grp; e < cnt; e += 8) {
        const unsigned w = g_ev[c * CAP + e];
        const float sg = (w & (1u << 17)) ? -1.f : 1.f;
        const float4 v = emb4[(size_t)(w & 8191u) * F4 + j];
        s.x += sg * v.x; s.y += sg * v.y; s.z += sg * v.z; s.w += sg * v.w;
    }

    __shared__ float4 red[512];
    red[tid] = s;
    __syncthreads();
    if (grp == 0) {
#pragma unroll
        for (int g = 1; g < 8; ++g) {
            const float4 a = red[tid + g * 64];
            s.x += a.x; s.y += a.y; s.z += a.z; s.w += a.w;
        }
        *reinterpret_cast<float4*>(&g_chunk[c * FEAT + (j << 2)]) = s;
    }
}

// ---- C: warp-per-feature exclusive scan over NCHUNK=512 chunk sums ----
__global__ void __launch_bounds__(32) chunk_scan_kernel()
{
    const int f = blockIdx.x;
    const int l = threadIdx.x;
    const int base = l * 16;

    float v[16];
#pragma unroll
    for (int i = 0; i < 16; ++i) v[i] = g_chunk[(base + i) * FEAT + f];
#pragma unroll
    for (int i = 1; i < 16; ++i) v[i] += v[i - 1];

    const float own = v[15];
    float incl = own;
#pragma unroll
    for (int d = 1; d < 32; d <<= 1) {
        const float t = __shfl_up_sync(0xffffffffu, incl, d);
        if (l >= d) incl += t;
    }
    const float excl = incl - own;

    g_chunk[(base + 0) * FEAT + f] = excl;
#pragma unroll
    for (int i = 1; i < 16; ++i)
        g_chunk[(base + i) * FEAT + f] = excl + v[i - 1];
}

// ---- D: apply. 512 blocks x 128 thr. Stage signed rows at sorted slots, then chain. ----
__global__ void __launch_bounds__(128) apply_kernel(
    const float* __restrict__ emb,
    float*       __restrict__ out)
{
    const int c   = blockIdx.x;
    const int tid = threadIdx.x;

    __shared__ float4   sdata[SH_EV][F4];   // signed event rows, in sorted order (54 KB)
    __shared__ unsigned swords[SH_EV];
    __shared__ int      spos[SH_EV];
    __shared__ int      hist[16], off[17], cur[16];

    int cnt = g_cnt[c]; if (cnt > CAP) cnt = CAP;
    const int scnt = cnt < SH_EV ? cnt : SH_EV;

    // load words + histogram
    if (tid < 16) hist[tid] = 0;
    __syncthreads();
    for (int e = tid; e < scnt; e += 128) {
        const unsigned w = g_ev[c * CAP + e];
        swords[e] = w;
        atomicAdd(&hist[(w >> 13) & 15], 1);
    }
    __syncthreads();
    if (tid == 0) {
        int a = 0;
#pragma unroll
        for (int i = 0; i < 16; ++i) { off[i] = a; cur[i] = a; a += hist[i]; }
        off[16] = a;
    }
    __syncthreads();
    for (int e = tid; e < scnt; e += 128)
        spos[e] = atomicAdd(&cur[(swords[e] >> 13) & 15], 1);
    __syncthreads();

    const int j    = tid & 63;       // float4 column
    const int pair = tid >> 6;       // 0/1
    const float4* emb4 = reinterpret_cast<const float4*>(emb);

    // stage signed rows at sorted slots — all gathers independent -> full MLP
    for (int e = pair; e < scnt; e += 2) {
        const unsigned w = swords[e];
        const float sg = (w & (1u << 17)) ? -1.f : 1.f;
        const float4 v = emb4[(size_t)(w & 8191u) * F4 + j];
        sdata[spos[e]][j] = make_float4(sg * v.x, sg * v.y, sg * v.z, sg * v.w);
    }
    __syncthreads();

    // chain phase: half 'pair' covers tokens [pair*8, pair*8+8)
    const int t0 = pair * 8;
    float4 run = *reinterpret_cast<const float4*>(&g_chunk[c * FEAT + (j << 2)]);

    // catch-up over staged events in tokens [0, t0)
    for (int e = 0; e < off[t0]; ++e) {
        const float4 v = sdata[e][j];
        run.x += v.x; run.y += v.y; run.z += v.z; run.w += v.w;
    }
    // overflow catch-up (slow path; not taken for this input)
    if (cnt > SH_EV) {
        for (int e = SH_EV; e < cnt; ++e) {
            const unsigned w = g_ev[c * CAP + e];
            const int tok = (w >> 13) & 15;
            if (tok < t0) {
                const float sg = (w & (1u << 17)) ? -1.f : 1.f;
                const float4 v = emb4[(size_t)(w & 8191u) * F4 + j];
                run.x += sg * v.x; run.y += sg * v.y; run.z += sg * v.z; run.w += sg * v.w;
            }
        }
    }

#pragma unroll
    for (int t = 0; t < 8; ++t) {
        const int tt = t0 + t;
        for (int e = off[tt]; e < off[tt + 1]; ++e) {
            const float4 v = sdata[e][j];
            run.x += v.x; run.y += v.y; run.z += v.z; run.w += v.w;
        }
        if (cnt > SH_EV) {   // overflow: add events landing exactly at this token
            for (int e = SH_EV; e < cnt; ++e) {
                const unsigned w = g_ev[c * CAP + e];
                if (((w >> 13) & 15) == tt) {
                    const float sg = (w & (1u << 17)) ? -1.f : 1.f;
                    const float4 v = emb4[(size_t)(w & 8191u) * F4 + j];
                    run.x += sg * v.x; run.y += sg * v.y; run.z += sg * v.z; run.w += sg * v.w;
                }
            }
        }
        *reinterpret_cast<float4*>(out + (size_t)(c * CHUNK + tt) * FEAT + (j << 2)) = run;
    }

    // self-reset for next graph replay
    __syncthreads();
    if (tid == 0) g_cnt[c] = 0;
}

extern "C" void kernel_launch(void* const* d_in, const int* in_sizes, int n_in,
                              void* d_out, int out_size)
{
    const float* emb    = (const float*)d_in[0];
    const int*   starts = (const int*)d_in[1];
    const int*   ends   = (const int*)d_in[2];
    const int*   nnp    = (const int*)d_in[3];
    float*       out    = (float*)d_out;

    classify_kernel<<<MAX_NODES / 256, 256>>>(starts, ends, nnp);
    chunk_sum_kernel<<<NCHUNK, 512>>>(emb);
    chunk_scan_kernel<<<FEAT, 32>>>();
    apply_kernel<<<NCHUNK, 128>>>(emb, out);
}